// round 1
// baseline (speedup 1.0000x reference)
#include <cuda_runtime.h>
#include <cuda_bf16.h>
#include <cstdint>

// ---------------- problem constants ----------------
#define HWB     105000          // H_BEV * W_BEV = 350*300
#define WBEV    300
#define HBEV    350
#define NIMG    2
#define AC      6               // NUM_ANGLES * NUM_CLASSES
#define TOPN    256             // PRE_NMS_TOP_N
#define CAP     16384           // collect buffer capacity

// output layout (float32, flattened concat of reference tuple)
#define OFF_BOX2D   0           // (2,256,4)  -> 2048
#define OFF_SCORES  2048        // (2,256)    -> 512
#define OFF_LABELS  2560        // (2,256)    -> 512
#define OFF_CORNERS 3072        // (2,256,8,3)-> 12288
#define OFF_FINAL   15360       // (2,256)    -> 512

// ---------------- device scratch (no allocations allowed) ----------------
__device__ unsigned int       g_hist[NIMG][65536];
__device__ unsigned int       g_cnt[NIMG];
__device__ unsigned int       g_cutoff[NIMG];
__device__ unsigned long long g_buf[NIMG][CAP];
__device__ int                g_selidx[NIMG][TOPN];
__device__ float              g_selscore[NIMG][TOPN];
__device__ float              g_bev[NIMG][TOPN][5];
__device__ unsigned char      g_valid[NIMG][TOPN];
__device__ int                g_clsidx[NIMG][TOPN];
__device__ unsigned int       g_adj[NIMG][TOPN][8];

// ---------------- helpers ----------------
__device__ __forceinline__ float sigmoidf_(float x) {
    if (x >= 0.f) { return 1.f / (1.f + expf(-x)); }
    float e = expf(x); return e / (1.f + e);
}

// monotone float -> uint mapping (total order)
__device__ __forceinline__ unsigned int f2key(float f) {
    unsigned int b = __float_as_uint(f);
    return (b & 0x80000000u) ? ~b : (b | 0x80000000u);
}

// ---------------- kernel 1: zero hist + counters ----------------
__global__ void k_init() {
    int i = blockIdx.x * blockDim.x + threadIdx.x;
    if (i < NIMG * 65536) ((unsigned int*)g_hist)[i] = 0u;
    if (i < NIMG) g_cnt[i] = 0u;
}

// ---------------- kernel 2: scores -> 16-bit-key histogram ----------------
__global__ void k_score(const float* __restrict__ cls, const float* __restrict__ ctr) {
    int n   = blockIdx.y;
    int loc = blockIdx.x * blockDim.x + threadIdx.x;
    if (loc >= HWB) return;
    const float* c0 = cls + (size_t)n * AC * HWB;
    const float* t0 = ctr + (size_t)n * 2  * HWB;
    float s0 = sigmoidf_(t0[loc]);
    float s1 = sigmoidf_(t0[HWB + loc]);
#pragma unroll
    for (int ch = 0; ch < 6; ch++) {
        float sc  = sigmoidf_(c0[ch * HWB + loc]);
        float ctv = (ch < 3) ? s0 : s1;
        float v   = (sc > 0.05f) ? sc * ctv : -1.0f;
        unsigned int key = f2key(v);
        atomicAdd(&g_hist[n][key >> 16], 1u);
    }
}

// ---------------- kernel 3: find cutoff bin (cum from top >= 256) ----------
__global__ void k_cutoff() {
    int n = blockIdx.x;
    __shared__ unsigned int csum[256];
    int t = threadIdx.x;
    unsigned int s = 0;
    for (int b = 0; b < 256; b++) s += g_hist[n][t * 256 + b];
    csum[t] = s;
    __syncthreads();
    if (t == 0) {
        unsigned int cum = 0;
        int chunk = 255;
        for (; chunk > 0; chunk--) {
            if (cum + csum[chunk] >= TOPN) break;
            cum += csum[chunk];
        }
        unsigned int cutoff = (unsigned int)(chunk * 256);
        for (int b = 255; b >= 0; b--) {
            unsigned int bin = chunk * 256 + b;
            cum += g_hist[n][bin];
            if (cum >= TOPN) { cutoff = bin; break; }
        }
        g_cutoff[n] = cutoff;
    }
}

// ---------------- kernel 4: collect all items with key16 >= cutoff --------
__global__ void k_collect(const float* __restrict__ cls, const float* __restrict__ ctr) {
    int n   = blockIdx.y;
    int loc = blockIdx.x * blockDim.x + threadIdx.x;
    if (loc >= HWB) return;
    unsigned int cutoff = g_cutoff[n];
    const float* c0 = cls + (size_t)n * AC * HWB;
    const float* t0 = ctr + (size_t)n * 2  * HWB;
    float s0 = sigmoidf_(t0[loc]);
    float s1 = sigmoidf_(t0[HWB + loc]);
#pragma unroll
    for (int ch = 0; ch < 6; ch++) {
        float sc  = sigmoidf_(c0[ch * HWB + loc]);
        float ctv = (ch < 3) ? s0 : s1;
        float v   = (sc > 0.05f) ? sc * ctv : -1.0f;
        unsigned int key = f2key(v);
        if ((key >> 16) >= cutoff) {
            unsigned int pos = atomicAdd(&g_cnt[n], 1u);
            if (pos < CAP) {
                unsigned int idx = (unsigned int)(loc * 6 + ch);
                g_buf[n][pos] = ((unsigned long long)key << 32) | (unsigned long long)(~idx);
            }
        }
    }
}

// ---------------- kernel 5: bitonic sort (desc key, asc idx), take 256 ----
__global__ void k_sort(float* __restrict__ out) {
    extern __shared__ unsigned long long sm[];
    int n   = blockIdx.x;
    int tid = threadIdx.x;
    int M = (int)g_cnt[n]; if (M > CAP) M = CAP;
    int P = 256; while (P < M) P <<= 1;
    for (int i = tid; i < P; i += blockDim.x) sm[i] = (i < M) ? g_buf[n][i] : 0ULL;
    __syncthreads();
    for (int k = 2; k <= P; k <<= 1) {
        for (int j = k >> 1; j > 0; j >>= 1) {
            for (int i = tid; i < P; i += blockDim.x) {
                int ixj = i ^ j;
                if (ixj > i) {
                    bool up = ((i & k) == 0);
                    unsigned long long a = sm[i], b = sm[ixj];
                    if (up ? (a < b) : (a > b)) { sm[i] = b; sm[ixj] = a; }
                }
            }
            __syncthreads();
        }
    }
    if (tid < TOPN) {
        unsigned long long v = sm[tid];
        unsigned int key = (unsigned int)(v >> 32);
        unsigned int idx = ~((unsigned int)(v & 0xFFFFFFFFu));
        unsigned int bits = (key & 0x80000000u) ? (key & 0x7FFFFFFFu) : ~key;
        float sc = __uint_as_float(bits);
        g_selidx[n][tid]   = (int)idx;
        g_selscore[n][tid] = sc;
        out[OFF_SCORES + n * TOPN + tid] = sc;
    }
}

// ---------------- kernel 6: per-item geometry, projection, bev ------------
__global__ void k_items(const float* __restrict__ reg, const float* __restrict__ calib,
                        const int* __restrict__ imgsz, const float* __restrict__ anchy,
                        float* __restrict__ out) {
    int n = blockIdx.x;
    int k = threadIdx.x;
    int idx   = g_selidx[n][k];
    float score = g_selscore[n][k];
    int loc = idx / 6;
    int ch  = idx % 6;
    int c   = idx % 3;
    int hh = loc / WBEV, ww = loc % WBEV;
    float x  = -30.0f + ((float)ww + 0.5f) * 0.2f;
    float z  =   0.0f + ((float)hh + 0.5f) * 0.2f;
    float ay = anchy[c];
    const float* rb = reg + (size_t)n * 144 * HWB;
    float P[12];
#pragma unroll
    for (int t = 0; t < 12; t++) P[t] = calib[n * 12 + t];

    float cx[8], cy[8], cz[8];
    float minu = 1e30f, minv = 1e30f, maxu = -1e30f, maxv = -1e30f;
    float sx = 0.f, sy = 0.f, sz = 0.f;
#pragma unroll
    for (int p = 0; p < 8; p++) {
        float X = rb[(size_t)(ch * 24 + p * 3 + 0) * HWB + loc] + x;
        float Y = rb[(size_t)(ch * 24 + p * 3 + 1) * HWB + loc] + ay;
        float Z = rb[(size_t)(ch * 24 + p * 3 + 2) * HWB + loc] + z;
        cx[p] = X; cy[p] = Y; cz[p] = Z;
        sx += X; sy += Y; sz += Z;
        float u = P[0] * X + P[1] * Y + P[2]  * Z + P[3];
        float v = P[4] * X + P[5] * Y + P[6]  * Z + P[7];
        float w = P[8] * X + P[9] * Y + P[10] * Z + P[11];
        float iu = u / w, iv = v / w;
        minu = fminf(minu, iu); maxu = fmaxf(maxu, iu);
        minv = fminf(minv, iv); maxv = fmaxf(maxv, iv);
    }
    float ih = (float)imgsz[n * 2 + 0];
    float iw = (float)imgsz[n * 2 + 1];
    float x1 = fminf(fmaxf(minu, 0.f), iw - 1.f);
    float y1 = fminf(fmaxf(minv, 0.f), ih - 1.f);
    float x2 = fminf(fmaxf(maxu, 0.f), iw - 1.f);
    float y2 = fminf(fmaxf(maxv, 0.f), ih - 1.f);
    bool valid = (score > 0.f) && (x2 - x1 >= 0.f) && (y2 - y1 >= 0.f);

    float cenx = sx * 0.125f, cenz = sz * 0.125f;
    float p0x = cx[0] - cenx, p0z = cz[0] - cenz;
    float p1x = cx[1] - cenx, p1z = cz[1] - cenz;
    float p2x = cx[2] - cenx, p2z = cz[2] - cenz;
    float elx = p0x - p1x, elz = p0z - p1z;
    float ewx = p1x - p2x, ewz = p1z - p2z;
    g_bev[n][k][0] = cenx;
    g_bev[n][k][1] = cenz;
    g_bev[n][k][2] = sqrtf(ewx * ewx + ewz * ewz);
    g_bev[n][k][3] = sqrtf(elx * elx + elz * elz);
    g_bev[n][k][4] = atan2f(elz, elx);
    g_valid[n][k]  = valid ? 1 : 0;
    g_clsidx[n][k] = c;

    float* b2d = out + OFF_BOX2D + ((size_t)n * TOPN + k) * 4;
    b2d[0] = x1; b2d[1] = y1; b2d[2] = x2; b2d[3] = y2;
    out[OFF_LABELS + n * TOPN + k] = (float)(c + 1);
    float* oc = out + OFF_CORNERS + ((size_t)n * TOPN + k) * 24;
#pragma unroll
    for (int p = 0; p < 8; p++) {
        oc[p * 3 + 0] = cx[p];
        oc[p * 3 + 1] = cy[p];
        oc[p * 3 + 2] = cz[p];
    }
}

// ---------------- rotated IoU (Sutherland–Hodgman, mirrors reference) -----
__device__ __forceinline__ void rect_corners(float x, float z, float w, float l, float r,
                                             float* qx, float* qz) {
    float c = cosf(r), s = sinf(r);
    const float LX[4] = {0.5f, -0.5f, -0.5f, 0.5f};
    const float WZ[4] = {0.5f, 0.5f, -0.5f, -0.5f};
#pragma unroll
    for (int k = 0; k < 4; k++) {
        float lx = LX[k] * l, wz = WZ[k] * w;
        qx[k] = x + c * lx - s * wz;
        qz[k] = z + s * lx + c * wz;
    }
}

__device__ float pair_iou(const float* b1, const float* b2) {
    float q1x[4], q1z[4], q2x[4], q2z[4];
    rect_corners(b1[0], b1[1], b1[2], b1[3], b1[4], q1x, q1z);
    rect_corners(b2[0], b2[1], b2[2], b2[3], b2[4], q2x, q2z);
    float px[8], pz[8];
#pragma unroll
    for (int t = 0; t < 8; t++) { px[t] = (t < 4) ? q1x[t] : 0.f; pz[t] = (t < 4) ? q1z[t] : 0.f; }
    int n = 4;
    for (int e = 0; e < 4; e++) {
        float Ax = q2x[e], Az = q2z[e];
        int e2 = (e + 1) & 3;
        float Bx = q2x[e2], Bz = q2z[e2];
        float ABx = Bx - Ax, ABz = Bz - Az;
        float ox[8], oz[8];
        int m = 0;
        int nn = (n > 8) ? 8 : n;
        for (int t = 0; t < nn; t++) {
            int t2 = (t + 1 < n) ? (t + 1) : 0;
            if (t2 > 7) t2 = 7;
            float cxx = px[t], czz = pz[t];
            float nxx = px[t2], nzz = pz[t2];
            float dc = ABx * (czz - Az) - ABz * (cxx - Ax);
            float dn = ABx * (nzz - Az) - ABz * (nxx - Ax);
            bool kc = (dc >= 0.f);
            bool kn = (dn >= 0.f);
            if (kc) { if (m < 8) { ox[m] = cxx; oz[m] = czz; } m++; }
            if (kc != kn) {
                float den = dc - dn;
                if (den == 0.f) den = 1.f;
                float s = dc / den;
                if (m < 8) { ox[m] = cxx + s * (nxx - cxx); oz[m] = czz + s * (nzz - czz); }
                m++;
            }
        }
        n = m;
#pragma unroll
        for (int t = 0; t < 8; t++) {
            px[t] = (t < m) ? ox[t] : 0.f;
            pz[t] = (t < m) ? oz[t] : 0.f;
        }
    }
    float s = 0.f;
    int nn = (n > 8) ? 8 : n;
    for (int t = 0; t < nn; t++) {
        int t2 = (t + 1 < n) ? (t + 1) : 0;
        if (t2 > 7) t2 = 7;
        s += px[t] * pz[t2] - px[t2] * pz[t];
    }
    float inter = 0.5f * fabsf(s);
    float uni = b1[2] * b1[3] + b2[2] * b2[3] - inter;
    return inter / fmaxf(uni, 1e-8f);
}

// ---------------- kernel 7: IoU adjacency bitmask (threshold 0.1) ---------
__global__ void k_iou() {
    int n = blockIdx.y, i = blockIdx.x, j = threadIdx.x;
    float b1[5], b2[5];
#pragma unroll
    for (int t = 0; t < 5; t++) { b1[t] = g_bev[n][i][t]; b2[t] = g_bev[n][j][t]; }
    float iou = pair_iou(b1, b2);
    unsigned int m = __ballot_sync(0xFFFFFFFFu, iou > 0.1f);
    if ((j & 31) == 0) g_adj[n][i][j >> 5] = m;
}

// ---------------- kernel 8: bit-matrix greedy NMS + final mask ------------
__global__ void k_nms(float* __restrict__ out) {
    int n = blockIdx.x;
    int k = threadIdx.x;
    __shared__ unsigned int sh_adj[TOPN][8];
    __shared__ unsigned int sh_vmask[3][8];
    __shared__ unsigned int sh_keep[3][8];
    __shared__ unsigned int sh_keepall[8];
    __shared__ float        sh_score[TOPN];
    __shared__ float        sh_thr;

#pragma unroll
    for (int w = 0; w < 8; w++) sh_adj[k][w] = g_adj[n][k][w];
    sh_score[k] = g_selscore[n][k];
    bool v  = (g_valid[n][k] != 0);
    int  cc = g_clsidx[n][k];
    int warp = k >> 5, lane = k & 31;
#pragma unroll
    for (int j = 0; j < 3; j++) {
        unsigned int m = __ballot_sync(0xFFFFFFFFu, v && (cc == j));
        if (lane == 0) sh_vmask[j][warp] = m;
    }
    __syncthreads();

    if (k < 3) {
        unsigned int supp[8];
#pragma unroll
        for (int w = 0; w < 8; w++) supp[w] = ~sh_vmask[k][w];
        for (int i = 0; i < 256; i++) {
            if (((supp[i >> 5] >> (i & 31)) & 1u) == 0u) {
                int wi = i >> 5;
                unsigned int mw = 0xFFFFFFFEu << (i & 31);  // bits strictly > i in word wi
#pragma unroll
                for (int w = 0; w < 8; w++) {
                    unsigned int m = (w < wi) ? 0u : ((w == wi) ? mw : 0xFFFFFFFFu);
                    supp[w] |= sh_adj[i][w] & m;
                }
            }
        }
#pragma unroll
        for (int w = 0; w < 8; w++) sh_keep[k][w] = ~supp[w];
    }
    __syncthreads();

    if (k == 0) {
        unsigned int ka[8];
        int cnt = 0;
        float kth = -1.f;
#pragma unroll
        for (int w = 0; w < 8; w++) {
            ka[w] = sh_keep[0][w] | sh_keep[1][w] | sh_keep[2][w];
            sh_keepall[w] = ka[w];
        }
        for (int t = 0; t < 256; t++) {
            if ((ka[t >> 5] >> (t & 31)) & 1u) {
                cnt++;
                if (cnt == 100) kth = sh_score[t];
            }
        }
        sh_thr = (cnt > 100) ? fmaxf(kth, 0.05f) : 0.05f;
    }
    __syncthreads();

    bool fin = (((sh_keepall[k >> 5] >> (k & 31)) & 1u) != 0u) && (sh_score[k] >= sh_thr);
    out[OFF_FINAL + n * TOPN + k] = fin ? 1.0f : 0.0f;
}

// ---------------- launch ----------------
extern "C" void kernel_launch(void* const* d_in, const int* in_sizes, int n_in,
                              void* d_out, int out_size) {
    const float* cls   = (const float*)d_in[0];
    const float* reg   = (const float*)d_in[1];
    const float* ctr   = (const float*)d_in[2];
    const float* calib = (const float*)d_in[3];
    const int*   imgsz = (const int*)d_in[4];
    const float* anchy = (const float*)d_in[5];
    float* out = (float*)d_out;

    cudaFuncSetAttribute(k_sort, cudaFuncAttributeMaxDynamicSharedMemorySize, CAP * 8);

    k_init<<<(NIMG * 65536 + 255) / 256, 256>>>();
    dim3 gScan((HWB + 255) / 256, NIMG);
    k_score<<<gScan, 256>>>(cls, ctr);
    k_cutoff<<<NIMG, 256>>>();
    k_collect<<<gScan, 256>>>(cls, ctr);
    k_sort<<<NIMG, 1024, CAP * 8>>>(out);
    k_items<<<NIMG, TOPN>>>(reg, calib, imgsz, anchy, out);
    dim3 gIou(TOPN, NIMG);
    k_iou<<<gIou, TOPN>>>();
    k_nms<<<NIMG, TOPN>>>(out);
}

// round 2
// speedup vs baseline: 2.8207x; 2.8207x over previous
#include <cuda_runtime.h>
#include <cuda_bf16.h>
#include <cstdint>

// ---------------- problem constants ----------------
#define HWB     105000          // H_BEV * W_BEV = 350*300
#define WBEV    300
#define NIMG    2
#define AC      6               // NUM_ANGLES * NUM_CLASSES
#define TOPN    256             // PRE_NMS_TOP_N
#define CAP     16384           // collect buffer capacity
#define NBIN    4096            // 12-bit key histogram

// output layout (float32, flattened concat of reference tuple)
#define OFF_BOX2D   0           // (2,256,4)  -> 2048
#define OFF_SCORES  2048        // (2,256)    -> 512
#define OFF_LABELS  2560        // (2,256)    -> 512
#define OFF_CORNERS 3072        // (2,256,8,3)-> 12288
#define OFF_FINAL   15360       // (2,256)    -> 512

// ---------------- device scratch (no allocations allowed) ----------------
__device__ unsigned int       g_hist[NIMG][NBIN];
__device__ unsigned int       g_cnt[NIMG];
__device__ unsigned int       g_cutoff[NIMG];
__device__ unsigned long long g_buf[NIMG][CAP];
__device__ int                g_selidx[NIMG][TOPN];
__device__ float              g_selscore[NIMG][TOPN];
__device__ unsigned char      g_valid[NIMG][TOPN];
__device__ int                g_clsidx[NIMG][TOPN];
__device__ unsigned int       g_adj[NIMG][TOPN][8];
// per-box precomputed geometry for IoU
__device__ float              g_qx[NIMG][TOPN][4];
__device__ float              g_qz[NIMG][TOPN][4];
__device__ float              g_area[NIMG][TOPN];
__device__ float              g_rad[NIMG][TOPN];
__device__ float              g_cx[NIMG][TOPN];
__device__ float              g_cz[NIMG][TOPN];

// ---------------- helpers ----------------
__device__ __forceinline__ float sigmoidf_(float x) {
    if (x >= 0.f) { return 1.f / (1.f + expf(-x)); }
    float e = expf(x); return e / (1.f + e);
}

// monotone float -> uint mapping (total order)
__device__ __forceinline__ unsigned int f2key(float f) {
    unsigned int b = __float_as_uint(f);
    return (b & 0x80000000u) ? ~b : (b | 0x80000000u);
}

// ---------------- kernel 1: zero hist + counters ----------------
__global__ void k_init() {
    int i = blockIdx.x * blockDim.x + threadIdx.x;
    if (i < NIMG * NBIN) ((unsigned int*)g_hist)[i] = 0u;
    if (i < NIMG) g_cnt[i] = 0u;
}

// ---------------- kernel 2: scores -> 12-bit-key shared histogram ---------
__global__ void k_score(const float* __restrict__ cls, const float* __restrict__ ctr) {
    __shared__ unsigned int sh[NBIN];
    int n    = blockIdx.y;
    int tid  = threadIdx.x;
    for (int i = tid; i < NBIN; i += blockDim.x) sh[i] = 0u;
    __syncthreads();

    int loc4 = (blockIdx.x * blockDim.x + tid) * 4;
    if (loc4 < HWB) {
        const float* c0 = cls + (size_t)n * AC * HWB;
        const float* t0 = ctr + (size_t)n * 2  * HWB;
        float4 t0v = *(const float4*)(t0 + loc4);
        float4 t1v = *(const float4*)(t0 + HWB + loc4);
        float s0[4] = { sigmoidf_(t0v.x), sigmoidf_(t0v.y), sigmoidf_(t0v.z), sigmoidf_(t0v.w) };
        float s1[4] = { sigmoidf_(t1v.x), sigmoidf_(t1v.y), sigmoidf_(t1v.z), sigmoidf_(t1v.w) };
#pragma unroll
        for (int ch = 0; ch < 6; ch++) {
            float4 cv = *(const float4*)(c0 + ch * HWB + loc4);
            float c4[4] = { cv.x, cv.y, cv.z, cv.w };
#pragma unroll
            for (int q = 0; q < 4; q++) {
                float sc  = sigmoidf_(c4[q]);
                float ctv = (ch < 3) ? s0[q] : s1[q];
                float v   = (sc > 0.05f) ? sc * ctv : -1.0f;
                atomicAdd(&sh[f2key(v) >> 20], 1u);
            }
        }
    }
    __syncthreads();
    for (int i = tid; i < NBIN; i += blockDim.x) {
        unsigned int c = sh[i];
        if (c) atomicAdd(&g_hist[n][i], c);
    }
}

// ---------------- kernel 3: find cutoff bin (cum from top >= 256) ---------
__global__ void k_cutoff() {
    int n = blockIdx.x;
    __shared__ unsigned int csum[256];
    int t = threadIdx.x;
    unsigned int s = 0;
    for (int b = 0; b < NBIN / 256; b++) s += g_hist[n][t * (NBIN / 256) + b];
    csum[t] = s;
    __syncthreads();
    if (t == 0) {
        unsigned int cum = 0;
        int chunk = 255;
        for (; chunk > 0; chunk--) {
            if (cum + csum[chunk] >= TOPN) break;
            cum += csum[chunk];
        }
        unsigned int cutoff = (unsigned int)(chunk * (NBIN / 256));
        for (int b = (NBIN / 256) - 1; b >= 0; b--) {
            unsigned int bin = chunk * (NBIN / 256) + b;
            cum += g_hist[n][bin];
            if (cum >= TOPN) { cutoff = bin; break; }
        }
        g_cutoff[n] = cutoff;
    }
}

// ---------------- kernel 4: collect all items with key12 >= cutoff --------
__global__ void k_collect(const float* __restrict__ cls, const float* __restrict__ ctr) {
    int n    = blockIdx.y;
    int loc4 = (blockIdx.x * blockDim.x + threadIdx.x) * 4;
    if (loc4 >= HWB) return;
    unsigned int cutoff = g_cutoff[n];
    const float* c0 = cls + (size_t)n * AC * HWB;
    const float* t0 = ctr + (size_t)n * 2  * HWB;
    float4 t0v = *(const float4*)(t0 + loc4);
    float4 t1v = *(const float4*)(t0 + HWB + loc4);
    float s0[4] = { sigmoidf_(t0v.x), sigmoidf_(t0v.y), sigmoidf_(t0v.z), sigmoidf_(t0v.w) };
    float s1[4] = { sigmoidf_(t1v.x), sigmoidf_(t1v.y), sigmoidf_(t1v.z), sigmoidf_(t1v.w) };
#pragma unroll
    for (int ch = 0; ch < 6; ch++) {
        float4 cv = *(const float4*)(c0 + ch * HWB + loc4);
        float c4[4] = { cv.x, cv.y, cv.z, cv.w };
#pragma unroll
        for (int q = 0; q < 4; q++) {
            float sc  = sigmoidf_(c4[q]);
            float ctv = (ch < 3) ? s0[q] : s1[q];
            float v   = (sc > 0.05f) ? sc * ctv : -1.0f;
            unsigned int key = f2key(v);
            if ((key >> 20) >= cutoff) {
                unsigned int pos = atomicAdd(&g_cnt[n], 1u);
                if (pos < CAP) {
                    unsigned int idx = (unsigned int)((loc4 + q) * 6 + ch);
                    g_buf[n][pos] = ((unsigned long long)key << 32) | (unsigned long long)(~idx);
                }
            }
        }
    }
}

// ---------------- kernel 5: bitonic sort (desc key, asc idx), take 256 ----
__global__ void k_sort(float* __restrict__ out) {
    extern __shared__ unsigned long long sm[];
    int n   = blockIdx.x;
    int tid = threadIdx.x;
    int M = (int)g_cnt[n]; if (M > CAP) M = CAP;
    int P = 256; while (P < M) P <<= 1;
    for (int i = tid; i < P; i += blockDim.x) sm[i] = (i < M) ? g_buf[n][i] : 0ULL;
    __syncthreads();
    for (int k = 2; k <= P; k <<= 1) {
        for (int j = k >> 1; j > 0; j >>= 1) {
            for (int i = tid; i < P; i += blockDim.x) {
                int ixj = i ^ j;
                if (ixj > i) {
                    bool up = ((i & k) == 0);
                    unsigned long long a = sm[i], b = sm[ixj];
                    if (up ? (a < b) : (a > b)) { sm[i] = b; sm[ixj] = a; }
                }
            }
            __syncthreads();
        }
    }
    if (tid < TOPN) {
        unsigned long long v = sm[tid];
        unsigned int key = (unsigned int)(v >> 32);
        unsigned int idx = ~((unsigned int)(v & 0xFFFFFFFFu));
        unsigned int bits = (key & 0x80000000u) ? (key & 0x7FFFFFFFu) : ~key;
        float sc = __uint_as_float(bits);
        g_selidx[n][tid]   = (int)idx;
        g_selscore[n][tid] = sc;
        out[OFF_SCORES + n * TOPN + tid] = sc;
    }
}

// ---------------- kernel 6: per-item geometry, projection, bev, corners ---
__global__ void k_items(const float* __restrict__ reg, const float* __restrict__ calib,
                        const int* __restrict__ imgsz, const float* __restrict__ anchy,
                        float* __restrict__ out) {
    int n = blockIdx.x;
    int k = threadIdx.x;
    int idx   = g_selidx[n][k];
    float score = g_selscore[n][k];
    int loc = idx / 6;
    int ch  = idx % 6;
    int c   = idx % 3;
    int hh = loc / WBEV, ww = loc % WBEV;
    float x  = -30.0f + ((float)ww + 0.5f) * 0.2f;
    float z  =   0.0f + ((float)hh + 0.5f) * 0.2f;
    float ay = anchy[c];
    const float* rb = reg + (size_t)n * 144 * HWB;
    float P[12];
#pragma unroll
    for (int t = 0; t < 12; t++) P[t] = calib[n * 12 + t];

    float cx[8], cy[8], cz[8];
    float minu = 1e30f, minv = 1e30f, maxu = -1e30f, maxv = -1e30f;
    float sx = 0.f, sy = 0.f, sz = 0.f;
#pragma unroll
    for (int p = 0; p < 8; p++) {
        float X = rb[(size_t)(ch * 24 + p * 3 + 0) * HWB + loc] + x;
        float Y = rb[(size_t)(ch * 24 + p * 3 + 1) * HWB + loc] + ay;
        float Z = rb[(size_t)(ch * 24 + p * 3 + 2) * HWB + loc] + z;
        cx[p] = X; cy[p] = Y; cz[p] = Z;
        sx += X; sy += Y; sz += Z;
        float u = P[0] * X + P[1] * Y + P[2]  * Z + P[3];
        float v = P[4] * X + P[5] * Y + P[6]  * Z + P[7];
        float w = P[8] * X + P[9] * Y + P[10] * Z + P[11];
        float iu = u / w, iv = v / w;
        minu = fminf(minu, iu); maxu = fmaxf(maxu, iu);
        minv = fminf(minv, iv); maxv = fmaxf(maxv, iv);
    }
    float ih = (float)imgsz[n * 2 + 0];
    float iw = (float)imgsz[n * 2 + 1];
    float x1 = fminf(fmaxf(minu, 0.f), iw - 1.f);
    float y1 = fminf(fmaxf(minv, 0.f), ih - 1.f);
    float x2 = fminf(fmaxf(maxu, 0.f), iw - 1.f);
    float y2 = fminf(fmaxf(maxv, 0.f), ih - 1.f);
    bool valid = (score > 0.f) && (x2 - x1 >= 0.f) && (y2 - y1 >= 0.f);

    float cenx = sx * 0.125f, cenz = sz * 0.125f;
    float p0x = cx[0] - cenx, p0z = cz[0] - cenz;
    float p1x = cx[1] - cenx, p1z = cz[1] - cenz;
    float p2x = cx[2] - cenx, p2z = cz[2] - cenz;
    float elx = p0x - p1x, elz = p0z - p1z;
    float ewx = p1x - p2x, ewz = p1z - p2z;
    float bw = sqrtf(ewx * ewx + ewz * ewz);   // bev w
    float bl = sqrtf(elx * elx + elz * elz);   // bev l
    float br = atan2f(elz, elx);               // bev r

    // precompute rotated-rect corners (matches _rect_corners: CCW)
    {
        float cr = cosf(br), sr = sinf(br);
        const float LX[4] = {0.5f, -0.5f, -0.5f, 0.5f};
        const float WZ[4] = {0.5f, 0.5f, -0.5f, -0.5f};
#pragma unroll
        for (int t = 0; t < 4; t++) {
            float lx = LX[t] * bl, wz = WZ[t] * bw;
            g_qx[n][k][t] = cenx + cr * lx - sr * wz;
            g_qz[n][k][t] = cenz + sr * lx + cr * wz;
        }
        g_area[n][k] = bw * bl;
        g_rad[n][k]  = 0.5f * sqrtf(bw * bw + bl * bl);
        g_cx[n][k]   = cenx;
        g_cz[n][k]   = cenz;
    }
    g_valid[n][k]  = valid ? 1 : 0;
    g_clsidx[n][k] = c;

    float* b2d = out + OFF_BOX2D + ((size_t)n * TOPN + k) * 4;
    b2d[0] = x1; b2d[1] = y1; b2d[2] = x2; b2d[3] = y2;
    out[OFF_LABELS + n * TOPN + k] = (float)(c + 1);
    float* oc = out + OFF_CORNERS + ((size_t)n * TOPN + k) * 24;
#pragma unroll
    for (int p = 0; p < 8; p++) {
        oc[p * 3 + 0] = cx[p];
        oc[p * 3 + 1] = cy[p];
        oc[p * 3 + 2] = cz[p];
    }
}

// ---- register-only Sutherland–Hodgman clip area (mirrors reference) ------
// All array indices are compile-time constants; compaction index `m` handled
// by predicated select-stores -> no local memory.
__device__ __forceinline__ float clip_area(const float* __restrict__ q1x,
                                           const float* __restrict__ q1z,
                                           const float* __restrict__ q2x,
                                           const float* __restrict__ q2z) {
    float px[8], pz[8];
#pragma unroll
    for (int t = 0; t < 8; t++) { px[t] = (t < 4) ? q1x[t] : 0.f; pz[t] = (t < 4) ? q1z[t] : 0.f; }
    int n = 4;
#pragma unroll
    for (int e = 0; e < 4; e++) {
        float Ax = q2x[e], Az = q2z[e];
        float Bx = q2x[(e + 1) & 3], Bz = q2z[(e + 1) & 3];
        float ABx = Bx - Ax, ABz = Bz - Az;
        float ox[8], oz[8];
#pragma unroll
        for (int s = 0; s < 8; s++) { ox[s] = 0.f; oz[s] = 0.f; }
        int m = 0;
#pragma unroll
        for (int t = 0; t < 8; t++) {
            bool live = (t < n);
            float cxx = px[t], czz = pz[t];
            float nxx, nzz;
            if (t < 7) {
                bool adv = (t + 1 < n);
                nxx = adv ? px[t + 1] : px[0];
                nzz = adv ? pz[t + 1] : pz[0];
            } else {
                // JAX clamp semantics: nxt_idx = (8 < n) ? 8(->7) : 0
                bool ovf = (8 < n);
                nxx = ovf ? px[7] : px[0];
                nzz = ovf ? pz[7] : pz[0];
            }
            float dc = ABx * (czz - Az) - ABz * (cxx - Ax);
            float dn = ABx * (nzz - Az) - ABz * (nxx - Ax);
            bool kc = (dc >= 0.f);
            bool kn = (dn >= 0.f);
            if (live && kc) {
#pragma unroll
                for (int s = 0; s < 8; s++) if (m == s) { ox[s] = cxx; oz[s] = czz; }
                m++;
            }
            if (live && (kc != kn)) {
                float den = dc - dn;
                if (den == 0.f) den = 1.f;
                float fr = dc / den;
                float ix = cxx + fr * (nxx - cxx);
                float iz = czz + fr * (nzz - czz);
#pragma unroll
                for (int s = 0; s < 8; s++) if (m == s) { ox[s] = ix; oz[s] = iz; }
                m++;
            }
        }
        n = m;
#pragma unroll
        for (int t = 0; t < 8; t++) { px[t] = ox[t]; pz[t] = oz[t]; }
    }
    float s = 0.f;
#pragma unroll
    for (int t = 0; t < 8; t++) {
        bool live = (t < n);
        float nxx, nzz;
        if (t < 7) {
            bool adv = (t + 1 < n);
            nxx = adv ? px[t + 1] : px[0];
            nzz = adv ? pz[t + 1] : pz[0];
        } else {
            bool ovf = (8 < n);
            nxx = ovf ? px[7] : px[0];
            nzz = ovf ? pz[7] : pz[0];
        }
        if (live) s += px[t] * nzz - nxx * pz[t];
    }
    return 0.5f * fabsf(s);
}

// ---------------- kernel 7: IoU adjacency bitmask (upper triangle) --------
__global__ void k_iou() {
    int n = blockIdx.y, i = blockIdx.x, j = threadIdx.x;
    __shared__ float sqx[TOPN][4], sqz[TOPN][4];
    __shared__ float sA[TOPN], sR[TOPN], sX[TOPN], sZ[TOPN];
#pragma unroll
    for (int t = 0; t < 4; t++) { sqx[j][t] = g_qx[n][j][t]; sqz[j][t] = g_qz[n][j][t]; }
    sA[j] = g_area[n][j]; sR[j] = g_rad[n][j];
    sX[j] = g_cx[n][j];   sZ[j] = g_cz[n][j];
    __syncthreads();

    bool hit = false;
    if (j > i) {
        float dx = sX[i] - sX[j], dz = sZ[i] - sZ[j];
        float rr = sR[i] + sR[j];
        if (dx * dx + dz * dz <= rr * rr) {
            float q1x[4], q1z[4], q2x[4], q2z[4];
#pragma unroll
            for (int t = 0; t < 4; t++) {
                q1x[t] = sqx[i][t]; q1z[t] = sqz[i][t];
                q2x[t] = sqx[j][t]; q2z[t] = sqz[j][t];
            }
            float inter = clip_area(q1x, q1z, q2x, q2z);
            float uni = sA[i] + sA[j] - inter;
            hit = (inter / fmaxf(uni, 1e-8f)) > 0.1f;
        }
    }
    unsigned int m = __ballot_sync(0xFFFFFFFFu, hit);
    if ((j & 31) == 0) g_adj[n][i][j >> 5] = m;
}

// ---------------- kernel 8: bit-matrix greedy NMS + final mask ------------
__global__ void k_nms(float* __restrict__ out) {
    int n = blockIdx.x;
    int k = threadIdx.x;
    __shared__ unsigned int sh_adj[TOPN][8];
    __shared__ unsigned int sh_vmask[3][8];
    __shared__ unsigned int sh_keep[3][8];
    __shared__ unsigned int sh_keepall[8];
    __shared__ float        sh_score[TOPN];
    __shared__ float        sh_thr;

#pragma unroll
    for (int w = 0; w < 8; w++) sh_adj[k][w] = g_adj[n][k][w];
    sh_score[k] = g_selscore[n][k];
    bool v  = (g_valid[n][k] != 0);
    int  cc = g_clsidx[n][k];
    int warp = k >> 5, lane = k & 31;
#pragma unroll
    for (int j = 0; j < 3; j++) {
        unsigned int m = __ballot_sync(0xFFFFFFFFu, v && (cc == j));
        if (lane == 0) sh_vmask[j][warp] = m;
    }
    __syncthreads();

    if (k < 3) {
        unsigned int supp[8];
#pragma unroll
        for (int w = 0; w < 8; w++) supp[w] = ~sh_vmask[k][w];
        for (int i = 0; i < 256; i++) {
            if (((supp[i >> 5] >> (i & 31)) & 1u) == 0u) {
                int wi = i >> 5;
                unsigned int mw = 0xFFFFFFFEu << (i & 31);  // bits strictly > i
#pragma unroll
                for (int w = 0; w < 8; w++) {
                    unsigned int m = (w < wi) ? 0u : ((w == wi) ? mw : 0xFFFFFFFFu);
                    supp[w] |= sh_adj[i][w] & m;
                }
            }
        }
#pragma unroll
        for (int w = 0; w < 8; w++) sh_keep[k][w] = ~supp[w];
    }
    __syncthreads();

    if (k == 0) {
        unsigned int ka[8];
        int cnt = 0;
        float kth = -1.f;
#pragma unroll
        for (int w = 0; w < 8; w++) {
            ka[w] = sh_keep[0][w] | sh_keep[1][w] | sh_keep[2][w];
            sh_keepall[w] = ka[w];
        }
        for (int t = 0; t < 256; t++) {
            if ((ka[t >> 5] >> (t & 31)) & 1u) {
                cnt++;
                if (cnt == 100) kth = sh_score[t];
            }
        }
        sh_thr = (cnt > 100) ? fmaxf(kth, 0.05f) : 0.05f;
    }
    __syncthreads();

    bool fin = (((sh_keepall[k >> 5] >> (k & 31)) & 1u) != 0u) && (sh_score[k] >= sh_thr);
    out[OFF_FINAL + n * TOPN + k] = fin ? 1.0f : 0.0f;
}

// ---------------- launch ----------------
extern "C" void kernel_launch(void* const* d_in, const int* in_sizes, int n_in,
                              void* d_out, int out_size) {
    const float* cls   = (const float*)d_in[0];
    const float* reg   = (const float*)d_in[1];
    const float* ctr   = (const float*)d_in[2];
    const float* calib = (const float*)d_in[3];
    const int*   imgsz = (const int*)d_in[4];
    const float* anchy = (const float*)d_in[5];
    float* out = (float*)d_out;

    cudaFuncSetAttribute(k_sort, cudaFuncAttributeMaxDynamicSharedMemorySize, CAP * 8);

    k_init<<<(NIMG * NBIN + 1023) / 1024, 1024>>>();
    dim3 gScan((HWB / 4 + 255) / 256, NIMG);
    k_score<<<gScan, 256>>>(cls, ctr);
    k_cutoff<<<NIMG, 256>>>();
    k_collect<<<gScan, 256>>>(cls, ctr);
    k_sort<<<NIMG, 1024, CAP * 8>>>(out);
    k_items<<<NIMG, TOPN>>>(reg, calib, imgsz, anchy, out);
    dim3 gIou(TOPN, NIMG);
    k_iou<<<gIou, TOPN>>>();
    k_nms<<<NIMG, TOPN>>>(out);
}